// round 4
// baseline (speedup 1.0000x reference)
#include <cuda_runtime.h>
#include <cuda_bf16.h>
#include <cstdint>

#define N_NODES 16384
#define DIM 512
#define SEG_CAP 64

// Scratch
__device__ float         g_Yf [(size_t)N_NODES * DIM];
__device__ __nv_bfloat16 g_Ybf[(size_t)N_NODES * DIM];
__device__ float         g_xr [(size_t)N_NODES * DIM];   // tf32-rounded x
__device__ float         g_Wr [(size_t)DIM * DIM];       // tf32-rounded W

__device__ __forceinline__ uint32_t f2tf32(float f) {
    uint32_t u;
    asm("cvt.rna.tf32.f32 %0, %1;" : "=r"(u) : "f"(f));
    return u;
}
__device__ __forceinline__ float bf_lo(uint32_t r) {
    uint32_t o; asm("prmt.b32 %0, %1, %2, 0x1044;" : "=r"(o) : "r"(r), "r"(0u));
    return __uint_as_float(o);
}
__device__ __forceinline__ float bf_hi(uint32_t r) {
    uint32_t o; asm("prmt.b32 %0, %1, %2, 0x3244;" : "=r"(o) : "r"(r), "r"(0u));
    return __uint_as_float(o);
}
__device__ __forceinline__ uint32_t smem_u32(const void* p) {
    uint32_t a;
    asm("{ .reg .u64 t; cvta.to.shared.u64 t, %1; cvt.u32.u64 %0, t; }" : "=r"(a) : "l"(p));
    return a;
}

#define CP_ASYNC16(saddr, gptr) \
    asm volatile("cp.async.cg.shared.global [%0], [%1], 16;" :: "r"(saddr), "l"(gptr) : "memory")
#define CP_COMMIT() asm volatile("cp.async.commit_group;" ::: "memory")
#define CP_WAIT1()  asm volatile("cp.async.wait_group 1;" ::: "memory")

// ---------------------------------------------------------------------------
// Kernel 0: tf32-rna prepass for x and W (exactly 2162688 float4s)
// ---------------------------------------------------------------------------
__global__ void __launch_bounds__(256) prepass(const float* __restrict__ x,
                                               const float* __restrict__ W) {
    const size_t i = ((size_t)blockIdx.x * 256 + threadIdx.x) * 4;
    const size_t NX = (size_t)N_NODES * DIM;
    if (i < NX) {
        float4 v = *(const float4*)(x + i);
        uint4 r = make_uint4(f2tf32(v.x), f2tf32(v.y), f2tf32(v.z), f2tf32(v.w));
        *(uint4*)((uint32_t*)g_xr + i) = r;
    } else {
        size_t j = i - NX;
        float4 v = *(const float4*)(W + j);
        uint4 r = make_uint4(f2tf32(v.x), f2tf32(v.y), f2tf32(v.z), f2tf32(v.w));
        *(uint4*)((uint32_t*)g_Wr + j) = r;
    }
}

// ---------------------------------------------------------------------------
// Kernel 1: Y = x @ W  (tf32 mma.sync, cp.async double-buffered)
// CTA tile 128x128, BK=32, 256 threads = 8 warps (4m x 2n), warp tile 32x64.
// Dynamic smem: As[2][128][36] + Bs[2][32][132] = 70656 bytes.
// ---------------------------------------------------------------------------
#define AS_OFF(s) ((s) * 4608)
#define BS_OFF(s) (9216 + (s) * 4224)
#define GEMM_SMEM 70656

__global__ void __launch_bounds__(256) gemm_xw() {
    extern __shared__ float sm[];
    const uint32_t smb = smem_u32(sm);

    const int tid  = threadIdx.x;
    const int wid  = tid >> 5;
    const int lane = tid & 31;
    const int wm   = wid & 3;
    const int wn   = wid >> 2;
    const int g    = lane >> 2;
    const int tg   = lane & 3;

    const int m0 = blockIdx.y * 128;
    const int n0 = blockIdx.x * 128;

    // --- prefetch helper (tile t into stage s) ---
    // A tile: 128 rows x 32 floats = 1024 16B chunks; id = l*256+tid
    // B tile:  32 rows x 128 floats = 1024 chunks
    const int a_row = tid >> 1;            // reused mapping pieces
    #define PREFETCH(t, s) do {                                                     \
        const int _kt = (t) * 32;                                                   \
        _Pragma("unroll")                                                           \
        for (int l = 0; l < 4; l++) {                                               \
            int id  = l * 256 + tid;                                                \
            int row = id >> 3, c = id & 7;                                          \
            const float* gp = g_xr + (size_t)(m0 + row) * DIM + _kt + c * 4;        \
            uint32_t sa = smb + (uint32_t)(AS_OFF(s) + row * 36 + c * 4) * 4;       \
            CP_ASYNC16(sa, gp);                                                     \
        }                                                                           \
        _Pragma("unroll")                                                           \
        for (int l = 0; l < 4; l++) {                                               \
            int id  = l * 256 + tid;                                                \
            int row = id >> 5, c = id & 31;                                         \
            const float* gp = g_Wr + (size_t)(_kt + row) * DIM + n0 + c * 4;        \
            uint32_t sa = smb + (uint32_t)(BS_OFF(s) + row * 132 + c * 4) * 4;      \
            CP_ASYNC16(sa, gp);                                                     \
        }                                                                           \
    } while (0)

    float c[2][8][4];
#pragma unroll
    for (int i = 0; i < 2; i++)
#pragma unroll
        for (int j = 0; j < 8; j++)
#pragma unroll
            for (int k = 0; k < 4; k++) c[i][j][k] = 0.f;

    PREFETCH(0, 0); CP_COMMIT();
    PREFETCH(1, 1); CP_COMMIT();

#pragma unroll 1
    for (int t = 0; t < 16; t++) {
        CP_WAIT1();
        __syncthreads();
        const int s = t & 1;
        const float* As = sm + AS_OFF(s);
        const float* Bs = sm + BS_OFF(s);

#pragma unroll
        for (int ks = 0; ks < 4; ks++) {
            const int kb = ks * 8;
            uint32_t a[2][4], b[8][2];
#pragma unroll
            for (int mi = 0; mi < 2; mi++) {
                int r = wm * 32 + mi * 16;
                a[mi][0] = __float_as_uint(As[(r + g    ) * 36 + kb + tg    ]);
                a[mi][1] = __float_as_uint(As[(r + g + 8) * 36 + kb + tg    ]);
                a[mi][2] = __float_as_uint(As[(r + g    ) * 36 + kb + tg + 4]);
                a[mi][3] = __float_as_uint(As[(r + g + 8) * 36 + kb + tg + 4]);
            }
#pragma unroll
            for (int ni = 0; ni < 8; ni++) {
                int nn = wn * 64 + ni * 8 + g;
                b[ni][0] = __float_as_uint(Bs[(kb + tg    ) * 132 + nn]);
                b[ni][1] = __float_as_uint(Bs[(kb + tg + 4) * 132 + nn]);
            }
#pragma unroll
            for (int mi = 0; mi < 2; mi++)
#pragma unroll
                for (int ni = 0; ni < 8; ni++) {
                    asm volatile(
                        "mma.sync.aligned.m16n8k8.row.col.f32.tf32.tf32.f32 "
                        "{%0,%1,%2,%3}, {%4,%5,%6,%7}, {%8,%9}, {%0,%1,%2,%3};"
                        : "+f"(c[mi][ni][0]), "+f"(c[mi][ni][1]),
                          "+f"(c[mi][ni][2]), "+f"(c[mi][ni][3])
                        : "r"(a[mi][0]), "r"(a[mi][1]), "r"(a[mi][2]), "r"(a[mi][3]),
                          "r"(b[ni][0]), "r"(b[ni][1]));
                }
        }
        __syncthreads();
        if (t + 2 < 16) PREFETCH(t + 2, s);
        CP_COMMIT();
    }
    (void)a_row;

    // Epilogue: write Y in fp32 and bf16
#pragma unroll
    for (int mi = 0; mi < 2; mi++) {
#pragma unroll
        for (int ni = 0; ni < 8; ni++) {
            int row0 = m0 + wm * 32 + mi * 16 + g;
            int col  = n0 + wn * 64 + ni * 8 + tg * 2;
            float2 v01 = make_float2(c[mi][ni][0], c[mi][ni][1]);
            float2 v23 = make_float2(c[mi][ni][2], c[mi][ni][3]);
            *(float2*)(g_Yf + (size_t)row0 * DIM + col)       = v01;
            *(float2*)(g_Yf + (size_t)(row0 + 8) * DIM + col) = v23;
            __nv_bfloat162 h01, h23;
            h01.x = __float2bfloat16_rn(v01.x); h01.y = __float2bfloat16_rn(v01.y);
            h23.x = __float2bfloat16_rn(v23.x); h23.y = __float2bfloat16_rn(v23.y);
            *(__nv_bfloat162*)(g_Ybf + (size_t)row0 * DIM + col)       = h01;
            *(__nv_bfloat162*)(g_Ybf + (size_t)(row0 + 8) * DIM + col) = h23;
        }
    }
}

// ---------------------------------------------------------------------------
// Kernel 2: fused sparse aggregation + residual + bias + relu
// (R2 structure; phase B now depth-2 software pipelined)
// ---------------------------------------------------------------------------
__global__ void __launch_bounds__(256) gcn_spmm(const float* __restrict__ A,
                                                const float* __restrict__ deg,
                                                const float* __restrict__ bias,
                                                float* __restrict__ out) {
    __shared__ uint16_t s_idx[8 * SEG_CAP];
    __shared__ int      s_cnt[8];
    __shared__ float    s_part[8 * DIM];

    const int row  = blockIdx.x;
    const int tid  = threadIdx.x;
    const int w    = tid >> 5;
    const int lane = tid & 31;
    const unsigned lml = (1u << lane) - 1u;

    // ---------------- Phase A: ballot compaction ----------------
    {
        const uint4* Ar = (const uint4*)(A + (size_t)row * N_NODES + w * 2048);
        int cnt = 0;
#pragma unroll 1
        for (int half = 0; half < 2; half++) {
            uint4 v[8];
#pragma unroll
            for (int k = 0; k < 8; k++)
                v[k] = __ldcs(Ar + (half * 8 + k) * 32 + lane);
#pragma unroll
            for (int k = 0; k < 8; k++) {
                unsigned nz  = v[k].x | v[k].y | v[k].z | v[k].w;
                unsigned any = __ballot_sync(0xFFFFFFFFu, nz != 0);
                if (any) {
                    int colbase = w * 2048 + ((half * 8 + k) * 32 + lane) * 4;
                    unsigned m;
                    m = __ballot_sync(0xFFFFFFFFu, v[k].x != 0);
                    if (v[k].x) { int p = cnt + __popc(m & lml); if (p < SEG_CAP) s_idx[w * SEG_CAP + p] = (uint16_t)(colbase + 0); }
                    cnt += __popc(m);
                    m = __ballot_sync(0xFFFFFFFFu, v[k].y != 0);
                    if (v[k].y) { int p = cnt + __popc(m & lml); if (p < SEG_CAP) s_idx[w * SEG_CAP + p] = (uint16_t)(colbase + 1); }
                    cnt += __popc(m);
                    m = __ballot_sync(0xFFFFFFFFu, v[k].z != 0);
                    if (v[k].z) { int p = cnt + __popc(m & lml); if (p < SEG_CAP) s_idx[w * SEG_CAP + p] = (uint16_t)(colbase + 2); }
                    cnt += __popc(m);
                    m = __ballot_sync(0xFFFFFFFFu, v[k].w != 0);
                    if (v[k].w) { int p = cnt + __popc(m & lml); if (p < SEG_CAP) s_idx[w * SEG_CAP + p] = (uint16_t)(colbase + 3); }
                    cnt += __popc(m);
                }
            }
        }
        if (lane == 0) s_cnt[w] = (cnt < SEG_CAP) ? cnt : SEG_CAP;
        __syncwarp();
    }

    // ---------------- Phase B: depth-2 pipelined gather ----------------
    float acc[16];
#pragma unroll
    for (int i = 0; i < 16; i++) acc[i] = 0.f;

    {
        const int n = s_cnt[w];
        const uint16_t* myidx = s_idx + w * SEG_CAP;
        uint4 pa[2], pb[2];
        if (n > 0) {
            const uint4* yp = (const uint4*)(g_Ybf + (size_t)myidx[0] * DIM);
            pa[0] = yp[lane]; pb[0] = yp[32 + lane];
        }
        if (n > 1) {
            const uint4* yp = (const uint4*)(g_Ybf + (size_t)myidx[1] * DIM);
            pa[1] = yp[lane]; pb[1] = yp[32 + lane];
        }
#pragma unroll 2
        for (int k = 0; k < n; k++) {
            uint4 ca = pa[k & 1];
            uint4 cb = pb[k & 1];
            if (k + 2 < n) {
                const uint4* yp = (const uint4*)(g_Ybf + (size_t)myidx[k + 2] * DIM);
                pa[k & 1] = yp[lane];
                pb[k & 1] = yp[32 + lane];
            }
            acc[0]  += bf_lo(ca.x); acc[1]  += bf_hi(ca.x);
            acc[2]  += bf_lo(ca.y); acc[3]  += bf_hi(ca.y);
            acc[4]  += bf_lo(ca.z); acc[5]  += bf_hi(ca.z);
            acc[6]  += bf_lo(ca.w); acc[7]  += bf_hi(ca.w);
            acc[8]  += bf_lo(cb.x); acc[9]  += bf_hi(cb.x);
            acc[10] += bf_lo(cb.y); acc[11] += bf_hi(cb.y);
            acc[12] += bf_lo(cb.z); acc[13] += bf_hi(cb.z);
            acc[14] += bf_lo(cb.w); acc[15] += bf_hi(cb.w);
        }
    }

    {
        float* p0 = s_part + w * DIM + 8 * lane;
        *(float4*)(p0 + 0)       = make_float4(acc[0], acc[1], acc[2], acc[3]);
        *(float4*)(p0 + 4)       = make_float4(acc[4], acc[5], acc[6], acc[7]);
        *(float4*)(p0 + 256)     = make_float4(acc[8], acc[9], acc[10], acc[11]);
        *(float4*)(p0 + 256 + 4) = make_float4(acc[12], acc[13], acc[14], acc[15]);
    }
    __syncthreads();

    // ---------------- Reduce + epilogue ----------------
    {
        const int col = tid * 2;
        float a0 = 0.f, a1 = 0.f;
#pragma unroll
        for (int ww = 0; ww < 8; ww++) {
            float2 p = *(const float2*)(s_part + ww * DIM + col);
            a0 += p.x; a1 += p.y;
        }
        const float di = 1.0f / deg[row];
        float2 ys = *(const float2*)(g_Yf + (size_t)row * DIM + col);
        float2 bb = *(const float2*)(bias + col);
        float o0 = fmaxf(di * a0 + (1.0f + di) * ys.x + bb.x, 0.f);
        float o1 = fmaxf(di * a1 + (1.0f + di) * ys.y + bb.y, 0.f);
        *(float2*)(out + (size_t)row * DIM + col) = make_float2(o0, o1);
    }
}

// ---------------------------------------------------------------------------
extern "C" void kernel_launch(void* const* d_in, const int* in_sizes, int n_in,
                              void* d_out, int out_size) {
    const float *x = nullptr, *A = nullptr, *deg = nullptr, *W = nullptr, *b = nullptr;
    for (int i = 0; i < n_in; i++) {
        long long sz = (long long)in_sizes[i];
        if      (sz == (long long)N_NODES * N_NODES) A   = (const float*)d_in[i];
        else if (sz == (long long)N_NODES * DIM)     x   = (const float*)d_in[i];
        else if (sz == (long long)DIM * DIM)         W   = (const float*)d_in[i];
        else if (sz == (long long)N_NODES)           deg = (const float*)d_in[i];
        else if (sz == (long long)DIM)               b   = (const float*)d_in[i];
    }

    cudaFuncSetAttribute(gemm_xw, cudaFuncAttributeMaxDynamicSharedMemorySize, GEMM_SMEM);

    prepass<<<8448, 256>>>(x, W);
    gemm_xw<<<dim3(4, 128), 256, GEMM_SMEM>>>();
    gcn_spmm<<<N_NODES, 256>>>(A, deg, b, (float*)d_out);
}